// round 10
// baseline (speedup 1.0000x reference)
#include <cuda_runtime.h>
#include <math.h>
#include <stdint.h>

// ---------------------------------------------------------------------------
// Quantizer: x [4,16,1024] f32, codebook [65536,16] f32.
// out[0:65536] = nearest codebook entry per token, [B,D,T]; out[65536] = loss.
//
// 4 launches:
//   prepA : per-block |.| maxima partials (no atomics)
//   prepB : reduce partials -> scales; quantize codebook; zero loss accum
//   scan  : int8 dp4a scores, per-(token, 256-code group) max,
//           COALESCED [group][token] store (4 MB)
//   finish: CTA-per-16-tokens; smem-transposed candidate selection;
//           exact fp32 rescue within rigorous 2E; fused deterministic loss
// ---------------------------------------------------------------------------

#define TOKENS   4096
#define NCODES   65536
#define DIM      16
#define GSZ      256                 // codes per group
#define NG       (NCODES / GSZ)      // 256 groups
#define PBLK     256
#define FT       16                  // tokens per finish CTA
#define FGRID    (TOKENS / FT)       // 256
#define NINF     __int_as_float(0xff800000)
#define FULL     0xffffffffu
#define LSCALE   4294967296.0        // 2^32 fixed-point loss scale

__device__ float    g_part[PBLK * 4];
__device__ unsigned g_scal[4];            // maxX, maxC, SAc (float bits)
__device__ int4     g_Bq[NCODES];         // packed int8 codes, 1 MB
__device__ int      g_bias[NCODES];       // bias in int score units
__device__ float    g_tb[(size_t)NG * TOKENS];  // [group][token], 4 MB
__device__ unsigned long long g_lsum;
__device__ unsigned g_cnt;

__device__ __forceinline__ void cpasync16(const void* dst_smem, const void* src) {
    unsigned s = (unsigned)__cvta_generic_to_shared(dst_smem);
    asm volatile("cp.async.cg.shared.global [%0], [%1], 16;" :: "r"(s), "l"(src));
}
#define CP_COMMIT() asm volatile("cp.async.commit_group;")
#define CP_WAIT0()  asm volatile("cp.async.wait_group 0;")

__device__ __forceinline__ int pack4(int a0, int a1, int a2, int a3) {
    return (a0 & 0xFF) | ((a1 & 0xFF) << 8) | ((a2 & 0xFF) << 16) | (a3 << 24);
}

// ---------------------------------------------------------------------------
// prepA: per-block maxima of |x|, max|c|, Sum|c| -> g_part.
// ---------------------------------------------------------------------------
__global__ __launch_bounds__(256) void prepA_kernel(const float* __restrict__ x,
                                                    const float* __restrict__ cb) {
    __shared__ float sm[3][256];
    int i = blockIdx.x * 256 + threadIdx.x;          // 0..65535
    float ax = fabsf(x[i]);
    const float4* c4 = (const float4*)(cb + (size_t)i * DIM);
    float mc = 0.0f, sa = 0.0f;
#pragma unroll
    for (int v = 0; v < 4; v++) {
        float4 q = c4[v];
        float a0 = fabsf(q.x), a1 = fabsf(q.y), a2 = fabsf(q.z), a3 = fabsf(q.w);
        mc = fmaxf(fmaxf(mc, fmaxf(a0, a1)), fmaxf(a2, a3));
        sa += a0; sa += a1; sa += a2; sa += a3;
    }
    sm[0][threadIdx.x] = ax; sm[1][threadIdx.x] = mc; sm[2][threadIdx.x] = sa;
    __syncthreads();
    for (int s = 128; s > 0; s >>= 1) {
        if (threadIdx.x < s) {
#pragma unroll
            for (int k = 0; k < 3; k++)
                sm[k][threadIdx.x] = fmaxf(sm[k][threadIdx.x], sm[k][threadIdx.x + s]);
        }
        __syncthreads();
    }
    if (threadIdx.x < 3) g_part[blockIdx.x * 4 + threadIdx.x] = sm[threadIdx.x][0];
}

// ---------------------------------------------------------------------------
// prepB: reduce partials (redundant per block), publish scales, quantize
// codebook, zero loss accumulator.
// ---------------------------------------------------------------------------
__global__ __launch_bounds__(256) void prepB_kernel(const float* __restrict__ cb) {
    __shared__ float sm[3][256];
    const int tid = threadIdx.x;
    sm[0][tid] = g_part[tid * 4 + 0];
    sm[1][tid] = g_part[tid * 4 + 1];
    sm[2][tid] = g_part[tid * 4 + 2];
    __syncthreads();
    for (int s = 128; s > 0; s >>= 1) {
        if (tid < s) {
#pragma unroll
            for (int k = 0; k < 3; k++)
                sm[k][tid] = fmaxf(sm[k][tid], sm[k][tid + s]);
        }
        __syncthreads();
    }
    const float maxX = sm[0][0], maxC = sm[1][0], SAc = sm[2][0];
    if (blockIdx.x == 0 && tid == 0) {
        g_scal[0] = __float_as_uint(maxX);
        g_scal[1] = __float_as_uint(maxC);
        g_scal[2] = __float_as_uint(SAc);
        g_lsum = 0ull;
        g_cnt  = 0u;
    }

    int i = blockIdx.x * 256 + tid;
    const float sx = maxX * (1.0f / 127.0f);
    const float sc = maxC * (1.0f / 127.0f);
    const float qc = 127.0f / maxC;
    const float4* c4 = (const float4*)(cb + (size_t)i * DIM);
    int q[DIM];
    float h = 0.0f;
#pragma unroll
    for (int v = 0; v < 4; v++) {
        float4 p = c4[v];
        h = fmaf(p.x, p.x, h); q[v * 4 + 0] = __float2int_rn(p.x * qc);
        h = fmaf(p.y, p.y, h); q[v * 4 + 1] = __float2int_rn(p.y * qc);
        h = fmaf(p.z, p.z, h); q[v * 4 + 2] = __float2int_rn(p.z * qc);
        h = fmaf(p.w, p.w, h); q[v * 4 + 3] = __float2int_rn(p.w * qc);
    }
    int4 w;
    w.x = pack4(q[0], q[1], q[2], q[3]);
    w.y = pack4(q[4], q[5], q[6], q[7]);
    w.z = pack4(q[8], q[9], q[10], q[11]);
    w.w = pack4(q[12], q[13], q[14], q[15]);
    g_Bq[i] = w;
    g_bias[i] = __float2int_rn(-0.5f * h / (sx * sc));
}

// ---------------------------------------------------------------------------
// scan: int8 dp4a. grid (4 batches, 256 groups), 256 thr, 4 tokens/thread,
// one 256-code group (5 KB smem) per CTA, 4 CTAs/SM. Coalesced tb store.
// ---------------------------------------------------------------------------
__global__ __launch_bounds__(256, 4) void scan_kernel(const float* __restrict__ x) {
    __shared__ int4 sQ[GSZ];     // 4 KB
    __shared__ int  sB[GSZ];     // 1 KB

    const int tid = threadIdx.x;
    const int batch = blockIdx.x;              // 0..3
    const int grp = blockIdx.y;                // 0..255
    const int c0 = grp * GSZ;

    cpasync16(&sQ[tid], &g_Bq[c0 + tid]);
    if (tid < 64) cpasync16(&sB[tid * 4], &g_bias[c0 + tid * 4]);
    CP_COMMIT();

    const float maxX = __uint_as_float(g_scal[0]);
    const float maxC = __uint_as_float(g_scal[1]);
    const float sx = maxX * (1.0f / 127.0f);
    const float sc = maxC * (1.0f / 127.0f);
    const float s  = sx * sc;
    const float qx = 127.0f / maxX;

    const float* xp = x + (size_t)batch * (DIM * 1024);
    int xq[4][4];
#pragma unroll
    for (int tk = 0; tk < 4; tk++) {
        int t = tk * 256 + tid;
#pragma unroll
        for (int w = 0; w < 4; w++) {
            int q0 = __float2int_rn(xp[(w * 4 + 0) * 1024 + t] * qx);
            int q1 = __float2int_rn(xp[(w * 4 + 1) * 1024 + t] * qx);
            int q2 = __float2int_rn(xp[(w * 4 + 2) * 1024 + t] * qx);
            int q3 = __float2int_rn(xp[(w * 4 + 3) * 1024 + t] * qx);
            xq[tk][w] = pack4(q0, q1, q2, q3);
        }
    }

    CP_WAIT0();
    __syncthreads();

    int m[4];
#pragma unroll
    for (int tk = 0; tk < 4; tk++) m[tk] = INT_MIN;
    const int4* b4 = (const int4*)sB;

#pragma unroll 4
    for (int g = 0; g < GSZ / 4; g++) {
        int4 bb = b4[g];
        int bias[4] = {bb.x, bb.y, bb.z, bb.w};
#pragma unroll
        for (int u = 0; u < 4; u++) {
            int4 q = sQ[g * 4 + u];
#pragma unroll
            for (int tk = 0; tk < 4; tk++) {
                int a = __dp4a(q.x, xq[tk][0], bias[u]);
                a = __dp4a(q.y, xq[tk][1], a);
                a = __dp4a(q.z, xq[tk][2], a);
                a = __dp4a(q.w, xq[tk][3], a);
                m[tk] = max(m[tk], a);
            }
        }
    }

    // coalesced store: [group][token]
#pragma unroll
    for (int tk = 0; tk < 4; tk++)
        g_tb[(size_t)grp * TOKENS + batch * 1024 + tk * 256 + tid] = (float)m[tk] * s;
}

// ---------------------------------------------------------------------------
// finish: CTA per 16 tokens. Bulk-coalesced tb load -> smem; warp-per-token
// (2 tokens/warp) exact rescue from smem; fused deterministic loss.
// ---------------------------------------------------------------------------
__global__ __launch_bounds__(256) void finish_kernel(const float* __restrict__ x,
                                                     const float* __restrict__ cb,
                                                     float* __restrict__ out,
                                                     int out_size) {
    __shared__ float tbs[NG][FT + 1];    // 256 x 17 x 4B = 17.4 KB
    __shared__ float sh_err[8];

    const int tid  = threadIdx.x;
    const int lane = tid & 31;
    const int warp = tid >> 5;
    const int t0   = blockIdx.x * FT;    // grid = 256, tokens in one batch

    // bulk-coalesced load of tb block [256 groups][16 tokens]
#pragma unroll
    for (int i = 0; i < 16; i++) {
        int idx = i * 256 + tid;                    // 0..4095
        int g = idx >> 4, j = idx & 15;
        tbs[g][j] = g_tb[(size_t)g * TOKENS + t0 + j];
    }
    __syncthreads();

    const float maxX = __uint_as_float(g_scal[0]);
    const float maxC = __uint_as_float(g_scal[1]);
    const float SAc  = __uint_as_float(g_scal[2]);
    const float sx = maxX * (1.0f / 127.0f);
    const float sc = maxC * (1.0f / 127.0f);

    float werr = 0.0f;

#pragma unroll
    for (int jj = 0; jj < 2; jj++) {
        const int j = warp * 2 + jj;
        const int token = t0 + j;
        const int bb = token >> 10, t = token & 1023;

        float xr[DIM];
        float SAx = 0.0f;
#pragma unroll
        for (int d = 0; d < DIM; d++) {
            xr[d] = x[(size_t)bb * (DIM * 1024) + d * 1024 + t];
            SAx += fabsf(xr[d]);
        }

        // lane's 8 group-maxima from smem (conflict-free: stride 17)
        float v[8];
        float m = NINF;
#pragma unroll
        for (int k = 0; k < 8; k++) {
            v[k] = tbs[k * 32 + lane][j];
            m = fmaxf(m, v[k]);
        }
#pragma unroll
        for (int off = 16; off > 0; off >>= 1)
            m = fmaxf(m, __shfl_xor_sync(FULL, m, off));

        const float E = 0.5f * sc * SAx + 0.5f * sx * SAc
                      + 16.0f * sx * sc + sx * sc + 1e-2f;
        const float thr = m - 2.0f * E;

        float best = NINF;
        int   bi   = 0x7fffffff;

#pragma unroll
        for (int k = 0; k < 8; k++) {
            unsigned bal = __ballot_sync(FULL, v[k] >= thr);
            while (bal) {
                int l = __ffs(bal) - 1;
                bal &= bal - 1;
                int cbase = (k * 32 + l) * GSZ;
#pragma unroll 4
                for (int r = 0; r < GSZ / 32; r++) {
                    int c = cbase + r * 32 + lane;
                    const float4* cr = (const float4*)(cb + (size_t)c * DIM);
                    float acc = 0.0f, h = 0.0f;
#pragma unroll
                    for (int v4 = 0; v4 < 4; v4++) {
                        float4 q = cr[v4];
                        acc = fmaf(q.x, xr[v4 * 4 + 0], acc); h = fmaf(q.x, q.x, h);
                        acc = fmaf(q.y, xr[v4 * 4 + 1], acc); h = fmaf(q.y, q.y, h);
                        acc = fmaf(q.z, xr[v4 * 4 + 2], acc); h = fmaf(q.z, q.z, h);
                        acc = fmaf(q.w, xr[v4 * 4 + 3], acc); h = fmaf(q.w, q.w, h);
                    }
                    float sscore = acc - 0.5f * h;
                    if (sscore > best || (sscore == best && c < bi)) {
                        best = sscore; bi = c;   // order-free first-index-wins
                    }
                }
            }
        }

#pragma unroll
        for (int off = 16; off > 0; off >>= 1) {
            float vb = __shfl_xor_sync(FULL, best, off);
            int   ib = __shfl_xor_sync(FULL, bi,   off);
            if (vb > best || (vb == best && ib < bi)) { best = vb; bi = ib; }
        }

        float e = 0.0f;
        if (lane < DIM) {
            float qd = cb[(size_t)bi * DIM + lane];
            float df = qd - xr[lane];
            e = df * df;
            out[(size_t)bb * (DIM * 1024) + lane * 1024 + t] = qd;
        }
#pragma unroll
        for (int off = 16; off > 0; off >>= 1)
            e += __shfl_xor_sync(FULL, e, off);
        werr += e;                      // all lanes hold the same sum
    }

    if (lane == 0) sh_err[warp] = werr;
    __syncthreads();
    if (tid == 0) {
        float ce = 0.0f;
#pragma unroll
        for (int w = 0; w < 8; w++) ce += sh_err[w];    // fixed order
        unsigned long long r =
            (unsigned long long)__double2ll_rn((double)ce * LSCALE);
        atomicAdd(&g_lsum, r);
        __threadfence();
        unsigned ticket = atomicAdd(&g_cnt, 1u);
        if (ticket == FGRID - 1 && out_size > NCODES) {
            double sum = (double)*(volatile unsigned long long*)&g_lsum;
            out[NCODES] = (float)(sum / LSCALE / (double)(TOKENS * DIM));
        }
    }
}

// ---------------------------------------------------------------------------
extern "C" void kernel_launch(void* const* d_in, const int* in_sizes, int n_in,
                              void* d_out, int out_size) {
    const float* x  = (const float*)d_in[0];   // [4,16,1024]
    const float* cb = (const float*)d_in[1];   // [65536,16]
    float* out = (float*)d_out;

    prepA_kernel<<<PBLK, 256>>>(x, cb);
    prepB_kernel<<<NCODES / 256, 256>>>(cb);

    dim3 grid(4, NG);
    scan_kernel<<<grid, 256>>>(x);

    finish_kernel<<<FGRID, 256>>>(x, cb, out, out_size);
}

// round 11
// speedup vs baseline: 2.3160x; 2.3160x over previous
#include <cuda_runtime.h>
#include <math.h>
#include <stdint.h>

// ---------------------------------------------------------------------------
// Quantizer: x [4,16,1024] f32, codebook [65536,16] f32.
// out[0:65536] = nearest codebook entry per token, [B,D,T]; out[65536] = loss.
//
// 4 launches:
//   prepA : per-block |.| maxima partials
//   prepB : reduce partials -> scales; quantize codebook; zero loss accum
//   scan  : int8 dp4a scores, per-(token, 64-code tile) max,
//           COALESCED [tile][token] store (16 MB, clean sectors)
//   finish: CTA-per-8-tokens; smem block of tile maxima; warp-per-token
//           exact fp32 rescue within rigorous 2E; fused deterministic loss
// ---------------------------------------------------------------------------

#define TOKENS   4096
#define NCODES   65536
#define DIM      16
#define STC      64                  // codes per tile (fine filter)
#define NST      (NCODES / STC)      // 1024 tiles
#define TPC      4                   // tiles per scan CTA
#define NGR      (NST / TPC)         // 256 scan groups
#define PBLK     256
#define FT       8                   // tokens per finish CTA
#define FGRID    (TOKENS / FT)       // 512
#define NINF     __int_as_float(0xff800000)
#define FULL     0xffffffffu
#define LSCALE   4294967296.0        // 2^32 fixed-point loss scale

__device__ float    g_part[PBLK * 4];
__device__ unsigned g_scal[4];            // maxX, maxC, SAc (float bits)
__device__ int4     g_Bq[NCODES];         // packed int8 codes, 1 MB
__device__ int      g_bias[NCODES];       // bias in int score units
__device__ float    g_tb[(size_t)NST * TOKENS];  // [tile][token], 16 MB
__device__ unsigned long long g_lsum;
__device__ unsigned g_cnt;

__device__ __forceinline__ void cpasync16(const void* dst_smem, const void* src) {
    unsigned s = (unsigned)__cvta_generic_to_shared(dst_smem);
    asm volatile("cp.async.cg.shared.global [%0], [%1], 16;" :: "r"(s), "l"(src));
}
#define CP_COMMIT() asm volatile("cp.async.commit_group;")
#define CP_WAIT0()  asm volatile("cp.async.wait_group 0;")

__device__ __forceinline__ int pack4(int a0, int a1, int a2, int a3) {
    return (a0 & 0xFF) | ((a1 & 0xFF) << 8) | ((a2 & 0xFF) << 16) | (a3 << 24);
}

// ---------------------------------------------------------------------------
// prepA: per-block maxima of |x|, max|c|, Sum|c| -> g_part.
// ---------------------------------------------------------------------------
__global__ __launch_bounds__(256) void prepA_kernel(const float* __restrict__ x,
                                                    const float* __restrict__ cb) {
    __shared__ float sm[3][256];
    int i = blockIdx.x * 256 + threadIdx.x;          // 0..65535
    float ax = fabsf(x[i]);
    const float4* c4 = (const float4*)(cb + (size_t)i * DIM);
    float mc = 0.0f, sa = 0.0f;
#pragma unroll
    for (int v = 0; v < 4; v++) {
        float4 q = c4[v];
        float a0 = fabsf(q.x), a1 = fabsf(q.y), a2 = fabsf(q.z), a3 = fabsf(q.w);
        mc = fmaxf(fmaxf(mc, fmaxf(a0, a1)), fmaxf(a2, a3));
        sa += a0; sa += a1; sa += a2; sa += a3;
    }
    sm[0][threadIdx.x] = ax; sm[1][threadIdx.x] = mc; sm[2][threadIdx.x] = sa;
    __syncthreads();
    for (int s = 128; s > 0; s >>= 1) {
        if (threadIdx.x < s) {
#pragma unroll
            for (int k = 0; k < 3; k++)
                sm[k][threadIdx.x] = fmaxf(sm[k][threadIdx.x], sm[k][threadIdx.x + s]);
        }
        __syncthreads();
    }
    if (threadIdx.x < 3) g_part[blockIdx.x * 4 + threadIdx.x] = sm[threadIdx.x][0];
}

// ---------------------------------------------------------------------------
// prepB: reduce partials (redundant per block), publish scales, quantize
// codebook, zero loss accumulator.
// ---------------------------------------------------------------------------
__global__ __launch_bounds__(256) void prepB_kernel(const float* __restrict__ cb) {
    __shared__ float sm[3][256];
    const int tid = threadIdx.x;
    sm[0][tid] = g_part[tid * 4 + 0];
    sm[1][tid] = g_part[tid * 4 + 1];
    sm[2][tid] = g_part[tid * 4 + 2];
    __syncthreads();
    for (int s = 128; s > 0; s >>= 1) {
        if (tid < s) {
#pragma unroll
            for (int k = 0; k < 3; k++)
                sm[k][tid] = fmaxf(sm[k][tid], sm[k][tid + s]);
        }
        __syncthreads();
    }
    const float maxX = sm[0][0], maxC = sm[1][0], SAc = sm[2][0];
    if (blockIdx.x == 0 && tid == 0) {
        g_scal[0] = __float_as_uint(maxX);
        g_scal[1] = __float_as_uint(maxC);
        g_scal[2] = __float_as_uint(SAc);
        g_lsum = 0ull;
        g_cnt  = 0u;
    }

    int i = blockIdx.x * 256 + tid;
    const float sx = maxX * (1.0f / 127.0f);
    const float sc = maxC * (1.0f / 127.0f);
    const float qc = 127.0f / maxC;
    const float4* c4 = (const float4*)(cb + (size_t)i * DIM);
    int q[DIM];
    float h = 0.0f;
#pragma unroll
    for (int v = 0; v < 4; v++) {
        float4 p = c4[v];
        h = fmaf(p.x, p.x, h); q[v * 4 + 0] = __float2int_rn(p.x * qc);
        h = fmaf(p.y, p.y, h); q[v * 4 + 1] = __float2int_rn(p.y * qc);
        h = fmaf(p.z, p.z, h); q[v * 4 + 2] = __float2int_rn(p.z * qc);
        h = fmaf(p.w, p.w, h); q[v * 4 + 3] = __float2int_rn(p.w * qc);
    }
    int4 w;
    w.x = pack4(q[0], q[1], q[2], q[3]);
    w.y = pack4(q[4], q[5], q[6], q[7]);
    w.z = pack4(q[8], q[9], q[10], q[11]);
    w.w = pack4(q[12], q[13], q[14], q[15]);
    g_Bq[i] = w;
    g_bias[i] = __float2int_rn(-0.5f * h / (sx * sc));
}

// ---------------------------------------------------------------------------
// scan: int8 dp4a. grid (4 batches, 256 groups), 256 thr, 4 tokens/thread,
// 4 x 64-code tiles (5 KB smem) per CTA, 4 CTAs/SM. Coalesced [tile][token]
// stores (256 consecutive tokens per (tile, tk) slice).
// ---------------------------------------------------------------------------
__global__ __launch_bounds__(256, 4) void scan_kernel(const float* __restrict__ x) {
    __shared__ int4 sQ[TPC * STC];     // 4 KB
    __shared__ int  sB[TPC * STC];     // 1 KB

    const int tid = threadIdx.x;
    const int batch = blockIdx.x;              // 0..3
    const int grp = blockIdx.y;                // 0..255
    const int c0 = grp * (TPC * STC);

    cpasync16(&sQ[tid], &g_Bq[c0 + tid]);
    if (tid < 64) cpasync16(&sB[tid * 4], &g_bias[c0 + tid * 4]);
    CP_COMMIT();

    const float maxX = __uint_as_float(g_scal[0]);
    const float maxC = __uint_as_float(g_scal[1]);
    const float sx = maxX * (1.0f / 127.0f);
    const float sc = maxC * (1.0f / 127.0f);
    const float s  = sx * sc;
    const float qx = 127.0f / maxX;

    const float* xp = x + (size_t)batch * (DIM * 1024);
    int xq[4][4];
#pragma unroll
    for (int tk = 0; tk < 4; tk++) {
        int t = tk * 256 + tid;
#pragma unroll
        for (int w = 0; w < 4; w++) {
            int q0 = __float2int_rn(xp[(w * 4 + 0) * 1024 + t] * qx);
            int q1 = __float2int_rn(xp[(w * 4 + 1) * 1024 + t] * qx);
            int q2 = __float2int_rn(xp[(w * 4 + 2) * 1024 + t] * qx);
            int q3 = __float2int_rn(xp[(w * 4 + 3) * 1024 + t] * qx);
            xq[tk][w] = pack4(q0, q1, q2, q3);
        }
    }

    CP_WAIT0();
    __syncthreads();

    const int4* b4 = (const int4*)sB;

#pragma unroll
    for (int st = 0; st < TPC; st++) {
        int m[4];
#pragma unroll
        for (int tk = 0; tk < 4; tk++) m[tk] = INT_MIN;
#pragma unroll 4
        for (int g = 0; g < STC / 4; g++) {
            int4 bb = b4[st * (STC / 4) + g];
            int bias[4] = {bb.x, bb.y, bb.z, bb.w};
#pragma unroll
            for (int u = 0; u < 4; u++) {
                int4 q = sQ[st * STC + g * 4 + u];
#pragma unroll
                for (int tk = 0; tk < 4; tk++) {
                    int a = __dp4a(q.x, xq[tk][0], bias[u]);
                    a = __dp4a(q.y, xq[tk][1], a);
                    a = __dp4a(q.z, xq[tk][2], a);
                    a = __dp4a(q.w, xq[tk][3], a);
                    m[tk] = max(m[tk], a);
                }
            }
        }
        // coalesced: per (st, tk), 256 threads hit 256 consecutive tokens
        const size_t row = (size_t)(grp * TPC + st) * TOKENS;
#pragma unroll
        for (int tk = 0; tk < 4; tk++)
            g_tb[row + batch * 1024 + tk * 256 + tid] = (float)m[tk] * s;
    }
}

// ---------------------------------------------------------------------------
// finish: CTA per 8 tokens (grid 512, 2 CTAs/SM, 36 KB smem). Bulk tb block
// load -> smem (pad 9, conflict-free); warp-per-token rescue; fused loss.
// ---------------------------------------------------------------------------
__global__ __launch_bounds__(256, 2) void finish_kernel(const float* __restrict__ x,
                                                        const float* __restrict__ cb,
                                                        float* __restrict__ out,
                                                        int out_size) {
    __shared__ float tbs[NST][FT + 1];   // 1024 x 9 x 4B = 36 KB
    __shared__ float sh_err[8];

    const int tid  = threadIdx.x;
    const int lane = tid & 31;
    const int warp = tid >> 5;
    const int t0   = blockIdx.x * FT;    // 8 tokens, same batch

    // bulk load: 8192 floats; idx -> tile = idx>>3, j = idx&7 (32B/row, 1 sector)
#pragma unroll
    for (int i = 0; i < 32; i++) {
        int idx = i * 256 + tid;
        int g = idx >> 3, j = idx & 7;
        tbs[g][j] = g_tb[(size_t)g * TOKENS + t0 + j];
    }
    __syncthreads();

    const float maxX = __uint_as_float(g_scal[0]);
    const float maxC = __uint_as_float(g_scal[1]);
    const float SAc  = __uint_as_float(g_scal[2]);
    const float sx = maxX * (1.0f / 127.0f);
    const float sc = maxC * (1.0f / 127.0f);

    const int j = warp;                  // warp -> token t0+j
    const int token = t0 + j;
    const int bb = token >> 10, t = token & 1023;

    float xr[DIM];
    float SAx = 0.0f;
#pragma unroll
    for (int d = 0; d < DIM; d++) {
        xr[d] = x[(size_t)bb * (DIM * 1024) + d * 1024 + t];
        SAx += fabsf(xr[d]);
    }

    // pass 1: token max over 1024 tiles (lane owns tiles k*32+lane)
    float m = NINF;
#pragma unroll
    for (int k = 0; k < 32; k++)
        m = fmaxf(m, tbs[k * 32 + lane][j]);
#pragma unroll
    for (int off = 16; off > 0; off >>= 1)
        m = fmaxf(m, __shfl_xor_sync(FULL, m, off));

    const float E = 0.5f * sc * SAx + 0.5f * sx * SAc
                  + 16.0f * sx * sc + sx * sc + 1e-2f;
    const float thr = m - 2.0f * E;

    // pass 2: candidate mask (bit k -> tile k*32+lane)
    unsigned cmask = 0u;
#pragma unroll
    for (int k = 0; k < 32; k++)
        if (tbs[k * 32 + lane][j] >= thr) cmask |= (1u << k);

    float best = NINF;
    int   bi   = 0x7fffffff;

    unsigned act = __ballot_sync(FULL, cmask != 0u);
    while (act) {
        int w = __ffs(act) - 1;
        act &= act - 1;
        unsigned msk = __shfl_sync(FULL, cmask, w);
        while (msk) {
            int k = __ffs(msk) - 1;
            msk &= msk - 1;
            int ti = k * 32 + w;
            int cbase = ti * STC;
#pragma unroll
            for (int half = 0; half < 2; half++) {
                int c = cbase + half * 32 + lane;
                const float4* cr = (const float4*)(cb + (size_t)c * DIM);
                float acc = 0.0f, h = 0.0f;
#pragma unroll
                for (int v4 = 0; v4 < 4; v4++) {
                    float4 q = cr[v4];
                    acc = fmaf(q.x, xr[v4 * 4 + 0], acc); h = fmaf(q.x, q.x, h);
                    acc = fmaf(q.y, xr[v4 * 4 + 1], acc); h = fmaf(q.y, q.y, h);
                    acc = fmaf(q.z, xr[v4 * 4 + 2], acc); h = fmaf(q.z, q.z, h);
                    acc = fmaf(q.w, xr[v4 * 4 + 3], acc); h = fmaf(q.w, q.w, h);
                }
                float sscore = acc - 0.5f * h;
                if (sscore > best || (sscore == best && c < bi)) {
                    best = sscore; bi = c;       // order-free first-index-wins
                }
            }
        }
    }

#pragma unroll
    for (int off = 16; off > 0; off >>= 1) {
        float vb = __shfl_xor_sync(FULL, best, off);
        int   ib = __shfl_xor_sync(FULL, bi,   off);
        if (vb > best || (vb == best && ib < bi)) { best = vb; bi = ib; }
    }

    float e = 0.0f;
    if (lane < DIM) {
        float qd = cb[(size_t)bi * DIM + lane];
        float df = qd - xr[lane];
        e = df * df;
        out[(size_t)bb * (DIM * 1024) + lane * 1024 + t] = qd;
    }
#pragma unroll
    for (int off = 16; off > 0; off >>= 1)
        e += __shfl_xor_sync(FULL, e, off);
    if (lane == 0) sh_err[warp] = e;

    // fused deterministic loss
    __syncthreads();
    if (tid == 0) {
        float ce = 0.0f;
#pragma unroll
        for (int w = 0; w < 8; w++) ce += sh_err[w];    // fixed order
        unsigned long long r =
            (unsigned long long)__double2ll_rn((double)ce * LSCALE);
        atomicAdd(&g_lsum, r);
        __threadfence();
        unsigned ticket = atomicAdd(&g_cnt, 1u);
        if (ticket == FGRID - 1 && out_size > NCODES) {
            double sum = (double)*(volatile unsigned long long*)&g_lsum;
            out[NCODES] = (float)(sum / LSCALE / (double)(TOKENS * DIM));
        }
    }
}

// ---------------------------------------------------------------------------
extern "C" void kernel_launch(void* const* d_in, const int* in_sizes, int n_in,
                              void* d_out, int out_size) {
    const float* x  = (const float*)d_in[0];   // [4,16,1024]
    const float* cb = (const float*)d_in[1];   // [65536,16]
    float* out = (float*)d_out;

    prepA_kernel<<<PBLK, 256>>>(x, cb);
    prepB_kernel<<<NCODES / 256, 256>>>(cb);

    dim3 grid(4, NGR);
    scan_kernel<<<grid, 256>>>(x);

    finish_kernel<<<FGRID, 256>>>(x, cb, out, out_size);
}